// round 11
// baseline (speedup 1.0000x reference)
#include <cuda_runtime.h>
#include <math.h>

#define Bz   128
#define Tz   1024
#define INz  256
#define Hz   512
#define H2z  1024
#define H4z  2048
#define OUTz 128
#define EPSz 1e-5f
#define NB   128   // persistent CTAs in scan kernel
#define NT   128   // threads per scan CTA

#define MSTR 130   // duplicated-A smem stride (floats) per k-row

// ---------------- device scratch (static allocation only) ----------------
__device__ float g_P0[(size_t)Tz * 2 * Bz * Hz];     // [t][dir][b][n], biases folded
__device__ float g_WTih0[2 * INz * Hz];              // [dir][k][n]
__device__ float g_WThh0[2 * Hz * Hz];
__device__ float g_WTih1[2 * H2z * Hz];
__device__ float g_WThh1[2 * Hz * Hz];
__device__ float g_WTfc1[H2z * H4z];                 // [k][n] n=2048
__device__ float g_WTfc2[H4z * OUTz];                // [k][o]
__device__ float g_h[2][4][Bz * Hz];                 // ping-pong states: slots 0,1=L0 f/b; 2,3=L1 f/b
__device__ float g_bn1[Bz * H2z];
__device__ float g_fc1[Bz * H4z];
__device__ float g_bn2[Bz * H4z];
__device__ unsigned g_bar_arrive;
__device__ volatile unsigned g_bar_gen;

// ---------------- f32x2 helpers ----------------
#define FMA2(acc, a, b) \
    asm("fma.rn.f32x2 %0, %1, %2, %0;" : "+l"(acc) : "l"(a), "l"(b))
#define LDS64(dst, addr) \
    asm volatile("ld.shared.b64 %0, [%1];" : "=l"(dst) : "r"(addr))
#define STS_SPLAT(addr, v) \
    asm volatile("st.shared.v2.f32 [%0], {%1, %2};" :: "r"(addr), "f"(v), "f"(v))
#define UNPACK2(lo, hi, p) \
    asm("mov.b64 {%0, %1}, %2;" : "=f"(lo), "=f"(hi) : "l"(p))

__device__ __forceinline__ unsigned smem_u32(const void* p) {
    return (unsigned)__cvta_generic_to_shared(p);
}

// ---------------- generic transpose: out[(d*C+c)*R+r] = in[(d*R+r)*C+c] ----------------
__global__ void k_tr(const float* __restrict__ in, float* __restrict__ out, int D, int R, int C) {
    long total = (long)D * R * C;
    long idx = (long)blockIdx.x * 256 + threadIdx.x;
    if (idx >= total) return;
    int r = (int)(idx % R);
    long q = idx / R;
    int c = (int)(q % C);
    int d = (int)(q / C);
    out[idx] = in[((long)d * R + r) * C + c];
}

__global__ void k_init_h(const float* __restrict__ h0) {
    int idx = blockIdx.x * 256 + threadIdx.x;
    if (idx < 4 * Bz * Hz) (&g_h[1][0][0])[idx] = h0[idx];
}

// ---------------- Phase A: P0[t][dir][b][n] = x_t @ Wih0^T + b_ih0 + b_hh0 ----------------
// rows r = b*T + t; BM=64 BN=64 BK=16, 256 threads, TM=TN=4, f32x2 inner loop.
__global__ void k_phase_a(const float* __restrict__ x,
                          const float* __restrict__ bih,
                          const float* __restrict__ bhh) {
    __shared__ __align__(16) float sA2[16 * MSTR];   // duplicated (a,a), kk-major
    __shared__ __align__(16) float sB[16 * 64];
    const int tid = threadIdx.x;
    const int r0  = blockIdx.x * 64;
    const int n0  = blockIdx.y * 64;
    const int dir = blockIdx.z;
    const int ty = tid >> 4, tx = tid & 15;
    const unsigned aBase = smem_u32(sA2);
    const unsigned bBase = smem_u32(sB);
    unsigned long long acc2[4][2] = {};
    const float* Wt = g_WTih0 + (size_t)dir * INz * Hz;

    for (int kc = 0; kc < INz; kc += 16) {
        __syncthreads();
        {
            // A stage: thread m=tid>>2 (0..63), kq=tid&3; duplicate each value
            int m = tid >> 2, kq = tid & 3;
            float4 v = __ldg(reinterpret_cast<const float4*>(x + (size_t)(r0 + m) * INz + kc + kq * 4));
            unsigned ad0 = aBase + (((kq * 4 + 0) * MSTR + m * 2) << 2);
            STS_SPLAT(ad0, v.x);
            STS_SPLAT(aBase + (((kq * 4 + 1) * MSTR + m * 2) << 2), v.y);
            STS_SPLAT(aBase + (((kq * 4 + 2) * MSTR + m * 2) << 2), v.z);
            STS_SPLAT(aBase + (((kq * 4 + 3) * MSTR + m * 2) << 2), v.w);
        }
        {
            int k = tid >> 4, nq = tid & 15;
            float4 v = __ldg(reinterpret_cast<const float4*>(Wt + (size_t)(kc + k) * Hz + n0 + nq * 4));
            *reinterpret_cast<float4*>(sB + k * 64 + nq * 4) = v;
        }
        __syncthreads();
        const unsigned aK = aBase + (ty * 4) * 8;
        const unsigned bK = bBase + tx * 16;
#pragma unroll
        for (int kk = 0; kk < 16; kk++) {
            unsigned long long b20, b21, a20, a21, a22, a23;
            LDS64(b20, bK + kk * 256);
            LDS64(b21, bK + kk * 256 + 8);
            LDS64(a20, aK + kk * (MSTR * 4) + 0);
            LDS64(a21, aK + kk * (MSTR * 4) + 8);
            LDS64(a22, aK + kk * (MSTR * 4) + 16);
            LDS64(a23, aK + kk * (MSTR * 4) + 24);
            FMA2(acc2[0][0], a20, b20); FMA2(acc2[0][1], a20, b21);
            FMA2(acc2[1][0], a21, b20); FMA2(acc2[1][1], a21, b21);
            FMA2(acc2[2][0], a22, b20); FMA2(acc2[2][1], a22, b21);
            FMA2(acc2[3][0], a23, b20); FMA2(acc2[3][1], a23, b21);
        }
    }
    int n = n0 + tx * 4;
    float4 bi = __ldg(reinterpret_cast<const float4*>(bih + dir * Hz + n));
    float4 bh = __ldg(reinterpret_cast<const float4*>(bhh + dir * Hz + n));
#pragma unroll
    for (int i = 0; i < 4; i++) {
        int r = r0 + ty * 4 + i;
        int t = r & (Tz - 1);
        int b_ = r >> 10;
        float l0, h0v, l1, h1v;
        UNPACK2(l0, h0v, acc2[i][0]);
        UNPACK2(l1, h1v, acc2[i][1]);
        float4 o;
        o.x = l0  + bi.x + bh.x;
        o.y = h0v + bi.y + bh.y;
        o.z = l1  + bi.z + bh.z;
        o.w = h1v + bi.w + bh.w;
        *reinterpret_cast<float4*>(g_P0 + (((size_t)t * 2 + dir) * Bz + b_) * Hz + n) = o;
    }
}

// ---------------- scan-phase GEMM core (f32x2): C[64x32] += A[m0..+63][0..511] * Wt ----------------
// A: [128][512] row-major; Wt: [512][512] row-major; BK=32, 16 chunks.
// Double-buffered, register-staged. A stored duplicated (splat) in smem, kk-major.
__device__ __forceinline__ void gemm512_f2(const float* __restrict__ A,
                                           const float* __restrict__ Wt,
                                           int m0, int n0, int tid,
                                           unsigned aBase, unsigned bBase,
                                           float* sBf,
                                           unsigned long long acc2[4][2]) {
    const int ty = tid >> 3, tx = tid & 7;
    const int lm  = tid >> 3;          // 0..15 (A rows, +u*16)
    const int lkq = tid & 7;           // A k-quad
    const int lk  = tid >> 3;          // B k row (+u*16)
    const int lnq = tid & 7;           // B n-quad
    const unsigned ABUF = 32u * MSTR * 4u;   // bytes per A buffer
    const unsigned BBUF = 32u * 32u * 4u;    // bytes per B buffer

    float4 rA[4], rB[2];

    // prologue: load chunk 0
#pragma unroll
    for (int u = 0; u < 4; u++)
        rA[u] = __ldcg(reinterpret_cast<const float4*>(A + (size_t)(m0 + lm + u * 16) * Hz + lkq * 4));
#pragma unroll
    for (int u = 0; u < 2; u++)
        rB[u] = __ldg(reinterpret_cast<const float4*>(Wt + (size_t)(lk + u * 16) * Hz + n0 + lnq * 4));
    // stage chunk 0 into buffer 0
#pragma unroll
    for (int u = 0; u < 4; u++) {
        int m2 = (lm + u * 16) * 2;
        STS_SPLAT(aBase + (((lkq * 4 + 0) * MSTR + m2) << 2), rA[u].x);
        STS_SPLAT(aBase + (((lkq * 4 + 1) * MSTR + m2) << 2), rA[u].y);
        STS_SPLAT(aBase + (((lkq * 4 + 2) * MSTR + m2) << 2), rA[u].z);
        STS_SPLAT(aBase + (((lkq * 4 + 3) * MSTR + m2) << 2), rA[u].w);
    }
#pragma unroll
    for (int u = 0; u < 2; u++)
        *reinterpret_cast<float4*>(sBf + (lk + u * 16) * 32 + lnq * 4) = rB[u];
    __syncthreads();

#pragma unroll 1
    for (int c = 0; c < 16; c++) {
        const int kc_next = (c + 1) * 32;
        if (c < 15) {
#pragma unroll
            for (int u = 0; u < 4; u++)
                rA[u] = __ldcg(reinterpret_cast<const float4*>(A + (size_t)(m0 + lm + u * 16) * Hz + kc_next + lkq * 4));
#pragma unroll
            for (int u = 0; u < 2; u++)
                rB[u] = __ldg(reinterpret_cast<const float4*>(Wt + (size_t)(kc_next + lk + u * 16) * Hz + n0 + lnq * 4));
        }
        const unsigned aK = aBase + (c & 1) * ABUF + (ty * 4) * 8;
        const unsigned bK = bBase + (c & 1) * BBUF + tx * 16;
#pragma unroll
        for (int kk = 0; kk < 32; kk++) {
            unsigned long long b20, b21, a20, a21, a22, a23;
            LDS64(b20, bK + kk * 128);
            LDS64(b21, bK + kk * 128 + 8);
            LDS64(a20, aK + kk * (MSTR * 4) + 0);
            LDS64(a21, aK + kk * (MSTR * 4) + 8);
            LDS64(a22, aK + kk * (MSTR * 4) + 16);
            LDS64(a23, aK + kk * (MSTR * 4) + 24);
            FMA2(acc2[0][0], a20, b20); FMA2(acc2[0][1], a20, b21);
            FMA2(acc2[1][0], a21, b20); FMA2(acc2[1][1], a21, b21);
            FMA2(acc2[2][0], a22, b20); FMA2(acc2[2][1], a22, b21);
            FMA2(acc2[3][0], a23, b20); FMA2(acc2[3][1], a23, b21);
        }
        if (c < 15) {
            const unsigned aN = aBase + ((c + 1) & 1) * ABUF;
            float* bN = sBf + ((c + 1) & 1) * (32 * 32);
#pragma unroll
            for (int u = 0; u < 4; u++) {
                int m2 = (lm + u * 16) * 2;
                STS_SPLAT(aN + (((lkq * 4 + 0) * MSTR + m2) << 2), rA[u].x);
                STS_SPLAT(aN + (((lkq * 4 + 1) * MSTR + m2) << 2), rA[u].y);
                STS_SPLAT(aN + (((lkq * 4 + 2) * MSTR + m2) << 2), rA[u].z);
                STS_SPLAT(aN + (((lkq * 4 + 3) * MSTR + m2) << 2), rA[u].w);
            }
#pragma unroll
            for (int u = 0; u < 2; u++)
                *reinterpret_cast<float4*>(bN + (lk + u * 16) * 32 + lnq * 4) = rB[u];
            __syncthreads();
        }
    }
}

__device__ __forceinline__ void grid_barrier(unsigned expect) {
    __syncthreads();
    if (threadIdx.x == 0) {
        __threadfence();
        if (atomicAdd(&g_bar_arrive, 1) == NB - 1) {
            g_bar_arrive = 0;
            __threadfence();
            g_bar_gen = expect;
        } else {
            while ((int)(g_bar_gen - expect) < 0) { __nanosleep(32); }
            __threadfence();
        }
    }
    __syncthreads();
}

// ---------------- Phase B: persistent sequential scan ----------------
// Phase p (0..T): CTAs 0..63 compute layer0(t=p); CTAs 64..127 compute layer1(t=p-1).
__global__ void __launch_bounds__(NT, 1) k_seq(const float* __restrict__ bih1,
                                               const float* __restrict__ bhh1) {
    __shared__ __align__(16) float sA2[2][32 * MSTR];
    __shared__ __align__(16) float sB[2][32 * 32];
    __shared__ unsigned sbase;
    const int tid = threadIdx.x, bid = blockIdx.x;
    if (tid == 0) sbase = g_bar_gen;
    __syncthreads();
    const unsigned base = sbase;
    const unsigned aBase = smem_u32(&sA2[0][0]);
    const unsigned bBase = smem_u32(&sB[0][0]);

    const bool isL0 = (bid < 64);
    const int l  = isL0 ? bid : bid - 64;
    const int dir = l >> 5;
    const int m0 = ((l >> 4) & 1) * 64;
    const int n0 = (l & 15) * 32;
    const int ty = tid >> 3, tx = tid & 7;

    for (int p = 0; p <= Tz; p++) {
        const int qa = (p + 1) & 1;   // "previous step" parity
        const int qw = p & 1;
        if (isL0) {
            if (p < Tz) {
                unsigned long long acc2[4][2] = {};
                gemm512_f2(&g_h[qa][dir][0], g_WThh0 + (size_t)dir * Hz * Hz,
                           m0, n0, tid, aBase, bBase, &sB[0][0], acc2);
                const float* p0 = g_P0 + (((size_t)p * 2 + dir) * Bz) * Hz;
                float* dst = &g_h[qw][dir][0];
#pragma unroll
                for (int i = 0; i < 4; i++) {
                    int row = m0 + ty * 4 + i;
                    float4 pv = __ldcg(reinterpret_cast<const float4*>(p0 + (size_t)row * Hz + n0 + tx * 4));
                    float l0v, h0v, l1v, h1v;
                    UNPACK2(l0v, h0v, acc2[i][0]);
                    UNPACK2(l1v, h1v, acc2[i][1]);
                    float4 o;
                    o.x = fmaxf(l0v + pv.x, 0.f);
                    o.y = fmaxf(h0v + pv.y, 0.f);
                    o.z = fmaxf(l1v + pv.z, 0.f);
                    o.w = fmaxf(h1v + pv.w, 0.f);
                    *reinterpret_cast<float4*>(dst + (size_t)row * Hz + n0 + tx * 4) = o;
                }
            }
        } else {
            if (p >= 1) {
                unsigned long long acc2[4][2] = {};
                const float* Aseg[3];
                const float* Wseg[3];
                Aseg[0] = &g_h[qa][0][0];
                Wseg[0] = g_WTih1 + (size_t)dir * H2z * Hz;
                Aseg[1] = &g_h[qa][1][0];
                Wseg[1] = g_WTih1 + (size_t)dir * H2z * Hz + (size_t)Hz * Hz;
                Aseg[2] = &g_h[qw][2 + dir][0];
                Wseg[2] = g_WThh1 + (size_t)dir * Hz * Hz;
#pragma unroll 1
                for (int s = 0; s < 3; s++)
                    gemm512_f2(Aseg[s], Wseg[s], m0, n0, tid, aBase, bBase, &sB[0][0], acc2);

                float4 bi = __ldg(reinterpret_cast<const float4*>(bih1 + dir * Hz + n0 + tx * 4));
                float4 bh = __ldg(reinterpret_cast<const float4*>(bhh1 + dir * Hz + n0 + tx * 4));
                float* dst = &g_h[qa][2 + dir][0];
#pragma unroll
                for (int i = 0; i < 4; i++) {
                    int row = m0 + ty * 4 + i;
                    float l0v, h0v, l1v, h1v;
                    UNPACK2(l0v, h0v, acc2[i][0]);
                    UNPACK2(l1v, h1v, acc2[i][1]);
                    float4 o;
                    o.x = fmaxf(l0v + bi.x + bh.x, 0.f);
                    o.y = fmaxf(h0v + bi.y + bh.y, 0.f);
                    o.z = fmaxf(l1v + bi.z + bh.z, 0.f);
                    o.w = fmaxf(h1v + bi.w + bh.w, 0.f);
                    *reinterpret_cast<float4*>(dst + (size_t)row * Hz + n0 + tx * 4) = o;
                }
            }
        }
        grid_barrier(base + (unsigned)p + 1u);
    }
}

// ---------------- Head ----------------
__global__ void k_bn1(const float* __restrict__ g, const float* __restrict__ b) {
    __shared__ float s1[128], s2[128];
    int j = blockIdx.x, t = threadIdx.x;
    float v = (j < Hz) ? g_h[1][2][t * Hz + j] : g_h[1][3][t * Hz + j - Hz];
    s1[t] = v; s2[t] = v * v;
    __syncthreads();
    for (int o = 64; o > 0; o >>= 1) {
        if (t < o) { s1[t] += s1[t + o]; s2[t] += s2[t + o]; }
        __syncthreads();
    }
    float mean = s1[0] * (1.f / 128.f);
    float var  = s2[0] * (1.f / 128.f) - mean * mean;
    float y = (v - mean) * rsqrtf(var + EPSz) * __ldg(g + j) + __ldg(b + j);
    g_bn1[t * H2z + j] = fmaxf(y, 0.f);
}

// fc1: [128,2048] = g_bn1[128,1024] @ WTfc1 + fc1_b  (pre-BN, no relu)
__global__ void k_fc1(const float* __restrict__ bias) {
    __shared__ float sA[64 * 17];
    __shared__ float sB[16 * 64];
    const int tid = threadIdx.x;
    const int m0 = blockIdx.x * 64;
    const int n0 = blockIdx.y * 64;
    const int ty = tid >> 4, tx = tid & 15;
    float acc[4][4] = {};
    for (int kc = 0; kc < H2z; kc += 16) {
        __syncthreads();
        {
            int m = tid >> 2, kq = tid & 3;
            float4 v = *reinterpret_cast<const float4*>(g_bn1 + (size_t)(m0 + m) * H2z + kc + kq * 4);
            sA[m * 17 + kq * 4 + 0] = v.x;
            sA[m * 17 + kq * 4 + 1] = v.y;
            sA[m * 17 + kq * 4 + 2] = v.z;
            sA[m * 17 + kq * 4 + 3] = v.w;
        }
        {
            int k = tid >> 4, nq = tid & 15;
            float4 v = __ldg(reinterpret_cast<const float4*>(g_WTfc1 + (size_t)(kc + k) * H4z + n0 + nq * 4));
            *reinterpret_cast<float4*>(sB + k * 64 + nq * 4) = v;
        }
        __syncthreads();
#pragma unroll
        for (int kk = 0; kk < 16; kk++) {
            float a0 = sA[(ty * 4 + 0) * 17 + kk];
            float a1 = sA[(ty * 4 + 1) * 17 + kk];
            float a2 = sA[(ty * 4 + 2) * 17 + kk];
            float a3 = sA[(ty * 4 + 3) * 17 + kk];
            float4 b = *reinterpret_cast<float4*>(sB + kk * 64 + tx * 4);
            acc[0][0] += a0 * b.x; acc[0][1] += a0 * b.y; acc[0][2] += a0 * b.z; acc[0][3] += a0 * b.w;
            acc[1][0] += a1 * b.x; acc[1][1] += a1 * b.y; acc[1][2] += a1 * b.z; acc[1][3] += a1 * b.w;
            acc[2][0] += a2 * b.x; acc[2][1] += a2 * b.y; acc[2][2] += a2 * b.z; acc[2][3] += a2 * b.w;
            acc[3][0] += a3 * b.x; acc[3][1] += a3 * b.y; acc[3][2] += a3 * b.z; acc[3][3] += a3 * b.w;
        }
    }
    int n = n0 + tx * 4;
    float4 bi = __ldg(reinterpret_cast<const float4*>(bias + n));
#pragma unroll
    for (int i = 0; i < 4; i++) {
        int m = m0 + ty * 4 + i;
        float4 o;
        o.x = acc[i][0] + bi.x;
        o.y = acc[i][1] + bi.y;
        o.z = acc[i][2] + bi.z;
        o.w = acc[i][3] + bi.w;
        *reinterpret_cast<float4*>(g_fc1 + (size_t)m * H4z + n) = o;
    }
}

__global__ void k_bn2(const float* __restrict__ g, const float* __restrict__ b) {
    __shared__ float s1[128], s2[128];
    int j = blockIdx.x, t = threadIdx.x;
    float v = g_fc1[t * H4z + j];
    s1[t] = v; s2[t] = v * v;
    __syncthreads();
    for (int o = 64; o > 0; o >>= 1) {
        if (t < o) { s1[t] += s1[t + o]; s2[t] += s2[t + o]; }
        __syncthreads();
    }
    float mean = s1[0] * (1.f / 128.f);
    float var  = s2[0] * (1.f / 128.f) - mean * mean;
    float y = (v - mean) * rsqrtf(var + EPSz) * __ldg(g + j) + __ldg(b + j);
    g_bn2[t * H4z + j] = fmaxf(y, 0.f);
}

__global__ void k_fc2(const float* __restrict__ fb, float* __restrict__ out) {
    __shared__ float s[H4z];
    int b = blockIdx.x, t = threadIdx.x;
    for (int i = t; i < H4z; i += 128) s[i] = g_bn2[b * H4z + i];
    __syncthreads();
    float acc = __ldg(fb + t);
#pragma unroll 4
    for (int k = 0; k < H4z; k++) acc += s[k] * __ldg(&g_WTfc2[k * OUTz + t]);
    out[b * OUTz + t] = 1.f / (1.f + expf(-acc));
}

// ---------------- launcher ----------------
extern "C" void kernel_launch(void* const* d_in, const int* in_sizes, int n_in,
                              void* d_out, int out_size) {
    const float* x    = (const float*)d_in[0];
    const float* h0   = (const float*)d_in[1];
    const float* Wih0 = (const float*)d_in[2];
    const float* Whh0 = (const float*)d_in[3];
    const float* bih0 = (const float*)d_in[4];
    const float* bhh0 = (const float*)d_in[5];
    const float* Wih1 = (const float*)d_in[6];
    const float* Whh1 = (const float*)d_in[7];
    const float* bih1 = (const float*)d_in[8];
    const float* bhh1 = (const float*)d_in[9];
    const float* bn1g = (const float*)d_in[10];
    const float* bn1b = (const float*)d_in[11];
    const float* fc1W = (const float*)d_in[12];
    const float* fc1b = (const float*)d_in[13];
    const float* bn2g = (const float*)d_in[14];
    const float* bn2b = (const float*)d_in[15];
    const float* fc2W = (const float*)d_in[16];
    const float* fc2b = (const float*)d_in[17];
    float* out = (float*)d_out;

    float* dWTih0; cudaGetSymbolAddress((void**)&dWTih0, g_WTih0);
    float* dWThh0; cudaGetSymbolAddress((void**)&dWThh0, g_WThh0);
    float* dWTih1; cudaGetSymbolAddress((void**)&dWTih1, g_WTih1);
    float* dWThh1; cudaGetSymbolAddress((void**)&dWThh1, g_WThh1);
    float* dWTfc1; cudaGetSymbolAddress((void**)&dWTfc1, g_WTfc1);
    float* dWTfc2; cudaGetSymbolAddress((void**)&dWTfc2, g_WTfc2);

    auto tr = [&](const float* in, float* o, int D, int R, int C) {
        long total = (long)D * R * C;
        k_tr<<<(unsigned)((total + 255) / 256), 256>>>(in, o, D, R, C);
    };
    tr(Wih0, dWTih0, 2, Hz, INz);
    tr(Whh0, dWThh0, 2, Hz, Hz);
    tr(Wih1, dWTih1, 2, Hz, H2z);
    tr(Whh1, dWThh1, 2, Hz, Hz);
    tr(fc1W, dWTfc1, 1, H4z, H2z);
    tr(fc2W, dWTfc2, 1, OUTz, H4z);

    k_init_h<<<(4 * Bz * Hz + 255) / 256, 256>>>(h0);

    k_phase_a<<<dim3((Bz * Tz) / 64, Hz / 64, 2), 256>>>(x, bih0, bhh0);

    k_seq<<<NB, NT>>>(bih1, bhh1);

    k_bn1<<<H2z, 128>>>(bn1g, bn1b);
    k_fc1<<<dim3(Bz / 64, H4z / 64), 256>>>(fc1b);
    k_bn2<<<H4z, 128>>>(bn2g, bn2b);
    k_fc2<<<Bz, 128>>>(fc2b, out);
}

// round 13
// speedup vs baseline: 1.5735x; 1.5735x over previous
#include <cuda_runtime.h>
#include <math.h>

#define Bz   128
#define Tz   1024
#define INz  256
#define Hz   512
#define H2z  1024
#define H4z  2048
#define OUTz 128
#define EPSz 1e-5f
#define NB   128   // persistent CTAs in scan kernel
#define NT   128   // threads per scan CTA

#define ASTR 32    // sA stride (floats), [kk][m] layout
#define BSTR 36    // sB stride (floats), [kk][n] layout, +4 pad for STS.128

// ---------------- device scratch (static allocation only) ----------------
__device__ float g_P0[(size_t)Tz * 2 * Bz * Hz];     // [t][dir][b][n], biases folded
__device__ float g_WTih0[2 * INz * Hz];              // [dir][k][n]
__device__ float g_WThh0[2 * Hz * Hz];
__device__ float g_WTih1[2 * H2z * Hz];
__device__ float g_WThh1[2 * Hz * Hz];
__device__ float g_WTfc1[H2z * H4z];                 // [k][n] n=2048
__device__ float g_WTfc2[H4z * OUTz];                // [k][o]
__device__ float g_h[2][4][Bz * Hz];                 // ping-pong states: slots 0,1=L0 f/b; 2,3=L1 f/b
__device__ float g_bn1[Bz * H2z];
__device__ float g_fc1[Bz * H4z];
__device__ float g_bn2[Bz * H4z];
__device__ unsigned g_bar_arrive;
__device__ volatile unsigned g_bar_gen;

// ---------------- generic transpose: out[(d*C+c)*R+r] = in[(d*R+r)*C+c] ----------------
__global__ void k_tr(const float* __restrict__ in, float* __restrict__ out, int D, int R, int C) {
    long total = (long)D * R * C;
    long idx = (long)blockIdx.x * 256 + threadIdx.x;
    if (idx >= total) return;
    int r = (int)(idx % R);
    long q = idx / R;
    int c = (int)(q % C);
    int d = (int)(q / C);
    out[idx] = in[((long)d * R + r) * C + c];
}

__global__ void k_init_h(const float* __restrict__ h0) {
    int idx = blockIdx.x * 256 + threadIdx.x;
    if (idx < 4 * Bz * Hz) (&g_h[1][0][0])[idx] = h0[idx];
}

// ---------------- Phase A: P0[t][dir][b][n] = x_t @ Wih0^T + b_ih0 + b_hh0 ----------------
// (identical to the R4 kernel that measured 34.7 ms total)
__global__ void k_phase_a(const float* __restrict__ x,
                          const float* __restrict__ bih,
                          const float* __restrict__ bhh) {
    __shared__ float sA[64 * 17];
    __shared__ float sB[16 * 64];
    const int tid = threadIdx.x;
    const int r0  = blockIdx.x * 64;
    const int n0  = blockIdx.y * 64;
    const int dir = blockIdx.z;
    const int ty = tid >> 4, tx = tid & 15;
    float acc[4][4] = {};
    const float* Wt = g_WTih0 + (size_t)dir * INz * Hz;

    for (int kc = 0; kc < INz; kc += 16) {
        __syncthreads();
        {
            int m = tid >> 2, kq = tid & 3;
            float4 v = __ldg(reinterpret_cast<const float4*>(x + (size_t)(r0 + m) * INz + kc + kq * 4));
            sA[m * 17 + kq * 4 + 0] = v.x;
            sA[m * 17 + kq * 4 + 1] = v.y;
            sA[m * 17 + kq * 4 + 2] = v.z;
            sA[m * 17 + kq * 4 + 3] = v.w;
        }
        {
            int k = tid >> 4, nq = tid & 15;
            float4 v = __ldg(reinterpret_cast<const float4*>(Wt + (size_t)(kc + k) * Hz + n0 + nq * 4));
            *reinterpret_cast<float4*>(sB + k * 64 + nq * 4) = v;
        }
        __syncthreads();
#pragma unroll
        for (int kk = 0; kk < 16; kk++) {
            float a0 = sA[(ty * 4 + 0) * 17 + kk];
            float a1 = sA[(ty * 4 + 1) * 17 + kk];
            float a2 = sA[(ty * 4 + 2) * 17 + kk];
            float a3 = sA[(ty * 4 + 3) * 17 + kk];
            float4 b = *reinterpret_cast<float4*>(sB + kk * 64 + tx * 4);
            acc[0][0] += a0 * b.x; acc[0][1] += a0 * b.y; acc[0][2] += a0 * b.z; acc[0][3] += a0 * b.w;
            acc[1][0] += a1 * b.x; acc[1][1] += a1 * b.y; acc[1][2] += a1 * b.z; acc[1][3] += a1 * b.w;
            acc[2][0] += a2 * b.x; acc[2][1] += a2 * b.y; acc[2][2] += a2 * b.z; acc[2][3] += a2 * b.w;
            acc[3][0] += a3 * b.x; acc[3][1] += a3 * b.y; acc[3][2] += a3 * b.z; acc[3][3] += a3 * b.w;
        }
    }
    int n = n0 + tx * 4;
    float4 bi = __ldg(reinterpret_cast<const float4*>(bih + dir * Hz + n));
    float4 bh = __ldg(reinterpret_cast<const float4*>(bhh + dir * Hz + n));
#pragma unroll
    for (int i = 0; i < 4; i++) {
        int r = r0 + ty * 4 + i;
        int t = r & (Tz - 1);
        int b_ = r >> 10;
        float4 o;
        o.x = acc[i][0] + bi.x + bh.x;
        o.y = acc[i][1] + bi.y + bh.y;
        o.z = acc[i][2] + bi.z + bh.z;
        o.w = acc[i][3] + bi.w + bh.w;
        *reinterpret_cast<float4*>(g_P0 + (((size_t)t * 2 + dir) * Bz + b_) * Hz + n) = o;
    }
}

// ---------------- scan GEMM core: C[32x32] += A[m0..+31][0..511] * Wt[0..511][n0..+31] ----------------
// A: [128][512] row-major; Wt rows of length 512 ([k][n]); K=512 (16 chunks of 32).
// sA stored TRANSPOSED [kk][m] (stride ASTR=32); sB [kk][n] (stride BSTR=36).
// Double-buffered, register-staged (same hazard structure as the proven R4 core).
__device__ __forceinline__ void gemm32(const float* __restrict__ A,
                                       const float* __restrict__ Wt,
                                       int m0, int n0, int tid,
                                       float (*sA)[32 * ASTR], float (*sB)[32 * BSTR],
                                       float acc[2][4]) {
    const int ty = tid >> 3, tx = tid & 7;
    const int lm  = tid & 31;          // A loader: m row
    const int lkq = (tid >> 5) * 8;    // A loader: k base (0,8,16,24)
    const int bk  = tid >> 2;          // B loader: k row
    const int bn  = (tid & 3) * 8;     // B loader: n base
    float4 rA0, rA1, rB0, rB1;

    // prologue: load + stage chunk 0
    rA0 = __ldcg(reinterpret_cast<const float4*>(A + (size_t)(m0 + lm) * Hz + lkq));
    rA1 = __ldcg(reinterpret_cast<const float4*>(A + (size_t)(m0 + lm) * Hz + lkq + 4));
    rB0 = __ldg (reinterpret_cast<const float4*>(Wt + (size_t)bk * Hz + n0 + bn));
    rB1 = __ldg (reinterpret_cast<const float4*>(Wt + (size_t)bk * Hz + n0 + bn + 4));
    {
        float* a = sA[0];
        float* b = sB[0];
        a[(lkq + 0) * ASTR + lm] = rA0.x;
        a[(lkq + 1) * ASTR + lm] = rA0.y;
        a[(lkq + 2) * ASTR + lm] = rA0.z;
        a[(lkq + 3) * ASTR + lm] = rA0.w;
        a[(lkq + 4) * ASTR + lm] = rA1.x;
        a[(lkq + 5) * ASTR + lm] = rA1.y;
        a[(lkq + 6) * ASTR + lm] = rA1.z;
        a[(lkq + 7) * ASTR + lm] = rA1.w;
        *reinterpret_cast<float4*>(b + bk * BSTR + bn)     = rB0;
        *reinterpret_cast<float4*>(b + bk * BSTR + bn + 4) = rB1;
    }
    __syncthreads();

#pragma unroll 1
    for (int c = 0; c < 16; c++) {
        if (c < 15) {
            const int kc = (c + 1) * 32;
            rA0 = __ldcg(reinterpret_cast<const float4*>(A + (size_t)(m0 + lm) * Hz + kc + lkq));
            rA1 = __ldcg(reinterpret_cast<const float4*>(A + (size_t)(m0 + lm) * Hz + kc + lkq + 4));
            rB0 = __ldg (reinterpret_cast<const float4*>(Wt + (size_t)(kc + bk) * Hz + n0 + bn));
            rB1 = __ldg (reinterpret_cast<const float4*>(Wt + (size_t)(kc + bk) * Hz + n0 + bn + 4));
        }
        const float* a = sA[c & 1];
        const float* b = sB[c & 1];
#pragma unroll
        for (int kk = 0; kk < 32; kk++) {
            float2 av = *reinterpret_cast<const float2*>(a + kk * ASTR + ty * 2);
            float4 bv = *reinterpret_cast<const float4*>(b + kk * BSTR + tx * 4);
            acc[0][0] += av.x * bv.x; acc[0][1] += av.x * bv.y;
            acc[0][2] += av.x * bv.z; acc[0][3] += av.x * bv.w;
            acc[1][0] += av.y * bv.x; acc[1][1] += av.y * bv.y;
            acc[1][2] += av.y * bv.z; acc[1][3] += av.y * bv.w;
        }
        if (c < 15) {
            float* a2 = sA[(c + 1) & 1];
            float* b2 = sB[(c + 1) & 1];
            a2[(lkq + 0) * ASTR + lm] = rA0.x;
            a2[(lkq + 1) * ASTR + lm] = rA0.y;
            a2[(lkq + 2) * ASTR + lm] = rA0.z;
            a2[(lkq + 3) * ASTR + lm] = rA0.w;
            a2[(lkq + 4) * ASTR + lm] = rA1.x;
            a2[(lkq + 5) * ASTR + lm] = rA1.y;
            a2[(lkq + 6) * ASTR + lm] = rA1.z;
            a2[(lkq + 7) * ASTR + lm] = rA1.w;
            *reinterpret_cast<float4*>(b2 + bk * BSTR + bn)     = rB0;
            *reinterpret_cast<float4*>(b2 + bk * BSTR + bn + 4) = rB1;
            __syncthreads();
        }
    }
}

__device__ __forceinline__ void grid_barrier(unsigned expect) {
    __syncthreads();
    if (threadIdx.x == 0) {
        __threadfence();
        if (atomicAdd(&g_bar_arrive, 1) == NB - 1) {
            g_bar_arrive = 0;
            __threadfence();
            g_bar_gen = expect;
        } else {
            while ((int)(g_bar_gen - expect) < 0) { __nanosleep(32); }
            __threadfence();
        }
    }
    __syncthreads();
}

// ---------------- Phase B: persistent sequential scan, layer-serial, load-balanced ----------------
// Per step t: PhaseA = L0(t) on ALL 128 CTAs (128 tiles 32x32, K=512) -> barrier
//             PhaseB = L1(t) on ALL 128 CTAs (128 tiles 32x32, K=3*512) -> barrier.
// Parities: L0(t) reads h0 slot (t+1)&1, writes slot t&1.
//           L1(t) reads h0 slot t&1 (same step, across barrier) + h1 slot (t+1)&1, writes h1 slot t&1.
__global__ void __launch_bounds__(NT, 1) k_seq(const float* __restrict__ bih1,
                                               const float* __restrict__ bhh1) {
    __shared__ __align__(16) float sA[2][32 * ASTR];
    __shared__ __align__(16) float sB[2][32 * BSTR];
    __shared__ unsigned sbase;
    const int tid = threadIdx.x, bid = blockIdx.x;
    if (tid == 0) sbase = g_bar_gen;
    __syncthreads();
    const unsigned base = sbase;

    const int dir = bid >> 6;
    const int m0  = ((bid >> 4) & 3) * 32;
    const int n0  = (bid & 15) * 32;
    const int ty = tid >> 3, tx = tid & 7;

    float4 bi = __ldg(reinterpret_cast<const float4*>(bih1 + dir * Hz + n0 + tx * 4));
    float4 bh = __ldg(reinterpret_cast<const float4*>(bhh1 + dir * Hz + n0 + tx * 4));
    const float bsum[4] = { bi.x + bh.x, bi.y + bh.y, bi.z + bh.z, bi.w + bh.w };

    for (int t = 0; t < Tz; t++) {
        const int qa = (t + 1) & 1;   // previous-step parity
        const int qw = t & 1;         // this-step parity
        // ---- Phase A: L0(t) ----
        {
            float acc[2][4] = {};
            gemm32(&g_h[qa][dir][0], g_WThh0 + (size_t)dir * Hz * Hz,
                   m0, n0, tid, sA, sB, acc);
            const float* p0 = g_P0 + (((size_t)t * 2 + dir) * Bz) * Hz;
            float* dst = &g_h[qw][dir][0];
#pragma unroll
            for (int i = 0; i < 2; i++) {
                int row = m0 + ty * 2 + i;
                float4 pv = __ldcg(reinterpret_cast<const float4*>(p0 + (size_t)row * Hz + n0 + tx * 4));
                float4 o;
                o.x = fmaxf(acc[i][0] + pv.x, 0.f);
                o.y = fmaxf(acc[i][1] + pv.y, 0.f);
                o.z = fmaxf(acc[i][2] + pv.z, 0.f);
                o.w = fmaxf(acc[i][3] + pv.w, 0.f);
                *reinterpret_cast<float4*>(dst + (size_t)row * Hz + n0 + tx * 4) = o;
            }
        }
        grid_barrier(base + 2u * (unsigned)t + 1u);
        // ---- Phase B: L1(t) ----
        {
            float acc[2][4] = {};
            gemm32(&g_h[qw][0][0], g_WTih1 + (size_t)dir * H2z * Hz,
                   m0, n0, tid, sA, sB, acc);
            gemm32(&g_h[qw][1][0], g_WTih1 + (size_t)dir * H2z * Hz + (size_t)Hz * Hz,
                   m0, n0, tid, sA, sB, acc);
            gemm32(&g_h[qa][2 + dir][0], g_WThh1 + (size_t)dir * Hz * Hz,
                   m0, n0, tid, sA, sB, acc);
            float* dst = &g_h[qw][2 + dir][0];
#pragma unroll
            for (int i = 0; i < 2; i++) {
                int row = m0 + ty * 2 + i;
                float4 o;
                o.x = fmaxf(acc[i][0] + bsum[0], 0.f);
                o.y = fmaxf(acc[i][1] + bsum[1], 0.f);
                o.z = fmaxf(acc[i][2] + bsum[2], 0.f);
                o.w = fmaxf(acc[i][3] + bsum[3], 0.f);
                *reinterpret_cast<float4*>(dst + (size_t)row * Hz + n0 + tx * 4) = o;
            }
        }
        grid_barrier(base + 2u * (unsigned)t + 2u);
    }
}

// ---------------- Head ----------------
__global__ void k_bn1(const float* __restrict__ g, const float* __restrict__ b) {
    __shared__ float s1[128], s2[128];
    int j = blockIdx.x, t = threadIdx.x;
    float v = (j < Hz) ? g_h[1][2][t * Hz + j] : g_h[1][3][t * Hz + j - Hz];
    s1[t] = v; s2[t] = v * v;
    __syncthreads();
    for (int o = 64; o > 0; o >>= 1) {
        if (t < o) { s1[t] += s1[t + o]; s2[t] += s2[t + o]; }
        __syncthreads();
    }
    float mean = s1[0] * (1.f / 128.f);
    float var  = s2[0] * (1.f / 128.f) - mean * mean;
    float y = (v - mean) * rsqrtf(var + EPSz) * __ldg(g + j) + __ldg(b + j);
    g_bn1[t * H2z + j] = fmaxf(y, 0.f);
}

// fc1: [128,2048] = g_bn1[128,1024] @ WTfc1 + fc1_b  (pre-BN, no relu)
__global__ void k_fc1(const float* __restrict__ bias) {
    __shared__ float sA[64 * 17];
    __shared__ float sB[16 * 64];
    const int tid = threadIdx.x;
    const int m0 = blockIdx.x * 64;
    const int n0 = blockIdx.y * 64;
    const int ty = tid >> 4, tx = tid & 15;
    float acc[4][4] = {};
    for (int kc = 0; kc < H2z; kc += 16) {
        __syncthreads();
        {
            int m = tid >> 2, kq = tid & 3;
            float4 v = *reinterpret_cast<const float4*>(g_bn1 + (size_t)(m0 + m) * H2z + kc + kq * 4);
            sA[m * 17 + kq * 4 + 0] = v.x;
            sA[m * 17 + kq * 4 + 1] = v.y;
            sA[m * 17 + kq * 4 + 2] = v.z;
            sA[m * 17 + kq * 4 + 3] = v.w;
        }
        {
            int k = tid >> 4, nq = tid & 15;
            float4 v = __ldg(reinterpret_cast<const float4*>(g_WTfc1 + (size_t)(kc + k) * H4z + n0 + nq * 4));
            *reinterpret_cast<float4*>(sB + k * 64 + nq * 4) = v;
        }
        __syncthreads();
#pragma unroll
        for (int kk = 0; kk < 16; kk++) {
            float a0 = sA[(ty * 4 + 0) * 17 + kk];
            float a1 = sA[(ty * 4 + 1) * 17 + kk];
            float a2 = sA[(ty * 4 + 2) * 17 + kk];
            float a3 = sA[(ty * 4 + 3) * 17 + kk];
            float4 b = *reinterpret_cast<float4*>(sB + kk * 64 + tx * 4);
            acc[0][0] += a0 * b.x; acc[0][1] += a0 * b.y; acc[0][2] += a0 * b.z; acc[0][3] += a0 * b.w;
            acc[1][0] += a1 * b.x; acc[1][1] += a1 * b.y; acc[1][2] += a1 * b.z; acc[1][3] += a1 * b.w;
            acc[2][0] += a2 * b.x; acc[2][1] += a2 * b.y; acc[2][2] += a2 * b.z; acc[2][3] += a2 * b.w;
            acc[3][0] += a3 * b.x; acc[3][1] += a3 * b.y; acc[3][2] += a3 * b.z; acc[3][3] += a3 * b.w;
        }
    }
    int n = n0 + tx * 4;
    float4 bi = __ldg(reinterpret_cast<const float4*>(bias + n));
#pragma unroll
    for (int i = 0; i < 4; i++) {
        int m = m0 + ty * 4 + i;
        float4 o;
        o.x = acc[i][0] + bi.x;
        o.y = acc[i][1] + bi.y;
        o.z = acc[i][2] + bi.z;
        o.w = acc[i][3] + bi.w;
        *reinterpret_cast<float4*>(g_fc1 + (size_t)m * H4z + n) = o;
    }
}

__global__ void k_bn2(const float* __restrict__ g, const float* __restrict__ b) {
    __shared__ float s1[128], s2[128];
    int j = blockIdx.x, t = threadIdx.x;
    float v = g_fc1[t * H4z + j];
    s1[t] = v; s2[t] = v * v;
    __syncthreads();
    for (int o = 64; o > 0; o >>= 1) {
        if (t < o) { s1[t] += s1[t + o]; s2[t] += s2[t + o]; }
        __syncthreads();
    }
    float mean = s1[0] * (1.f / 128.f);
    float var  = s2[0] * (1.f / 128.f) - mean * mean;
    float y = (v - mean) * rsqrtf(var + EPSz) * __ldg(g + j) + __ldg(b + j);
    g_bn2[t * H4z + j] = fmaxf(y, 0.f);
}

__global__ void k_fc2(const float* __restrict__ fb, float* __restrict__ out) {
    __shared__ float s[H4z];
    int b = blockIdx.x, t = threadIdx.x;
    for (int i = t; i < H4z; i += 128) s[i] = g_bn2[b * H4z + i];
    __syncthreads();
    float acc = __ldg(fb + t);
#pragma unroll 4
    for (int k = 0; k < H4z; k++) acc += s[k] * __ldg(&g_WTfc2[k * OUTz + t]);
    out[b * OUTz + t] = 1.f / (1.f + expf(-acc));
}

// ---------------- launcher ----------------
extern "C" void kernel_launch(void* const* d_in, const int* in_sizes, int n_in,
                              void* d_out, int out_size) {
    const float* x    = (const float*)d_in[0];
    const float* h0   = (const float*)d_in[1];
    const float* Wih0 = (const float*)d_in[2];
    const float* Whh0 = (const float*)d_in[3];
    const float* bih0 = (const float*)d_in[4];
    const float* bhh0 = (const float*)d_in[5];
    const float* Wih1 = (const float*)d_in[6];
    const float* Whh1 = (const float*)d_in[7];
    const float* bih1 = (const float*)d_in[8];
    const float* bhh1 = (const float*)d_in[9];
    const float* bn1g = (const float*)d_in[10];
    const float* bn1b = (const float*)d_in[11];
    const float* fc1W = (const float*)d_in[12];
    const float* fc1b = (const float*)d_in[13];
    const float* bn2g = (const float*)d_in[14];
    const float* bn2b = (const float*)d_in[15];
    const float* fc2W = (const float*)d_in[16];
    const float* fc2b = (const float*)d_in[17];
    float* out = (float*)d_out;

    float* dWTih0; cudaGetSymbolAddress((void**)&dWTih0, g_WTih0);
    float* dWThh0; cudaGetSymbolAddress((void**)&dWThh0, g_WThh0);
    float* dWTih1; cudaGetSymbolAddress((void**)&dWTih1, g_WTih1);
    float* dWThh1; cudaGetSymbolAddress((void**)&dWThh1, g_WThh1);
    float* dWTfc1; cudaGetSymbolAddress((void**)&dWTfc1, g_WTfc1);
    float* dWTfc2; cudaGetSymbolAddress((void**)&dWTfc2, g_WTfc2);

    auto tr = [&](const float* in, float* o, int D, int R, int C) {
        long total = (long)D * R * C;
        k_tr<<<(unsigned)((total + 255) / 256), 256>>>(in, o, D, R, C);
    };
    tr(Wih0, dWTih0, 2, Hz, INz);
    tr(Whh0, dWThh0, 2, Hz, Hz);
    tr(Wih1, dWTih1, 2, Hz, H2z);
    tr(Whh1, dWThh1, 2, Hz, Hz);
    tr(fc1W, dWTfc1, 1, H4z, H2z);
    tr(fc2W, dWTfc2, 1, OUTz, H4z);

    k_init_h<<<(4 * Bz * Hz + 255) / 256, 256>>>(h0);

    k_phase_a<<<dim3((Bz * Tz) / 64, Hz / 64, 2), 256>>>(x, bih0, bhh0);

    k_seq<<<NB, NT>>>(bih1, bhh1);

    k_bn1<<<H2z, 128>>>(bn1g, bn1b);
    k_fc1<<<dim3(Bz / 64, H4z / 64), 256>>>(fc1b);
    k_bn2<<<H4z, 128>>>(bn2g, bn2b);
    k_fc2<<<Bz, 128>>>(fc2b, out);
}